// round 11
// baseline (speedup 1.0000x reference)
#include <cuda_runtime.h>
#include <math.h>

#define V 50257
#define E 1024
#define H 1024
#define L 52

#define OUT_CHUNK 16                       /* rows per warp in k_out */
#define OUT_BLOCKS 393                     /* ceil(V / (8*16)) */

// ---- device scratch (no allocs allowed) ----
__device__ float g_emb[H];
__device__ float g_attn[H];
__device__ float g_x_p[2 * H];      // comb partials (K-split)
__device__ float g_gi[3 * H];
__device__ float g_gh[3 * H];
__device__ float2 g_ms[OUT_BLOCKS]; // per-block online (max, sumexp)

__device__ __forceinline__ float warp_reduce_sum(float v) {
#pragma unroll
    for (int o = 16; o; o >>= 1) v += __shfl_down_sync(0xffffffffu, v, o);
    return v;
}

__device__ __forceinline__ void ms_merge(float& m, float& s, float m2, float s2) {
    if (s2 == 0.f) return;
    if (s == 0.f) { m = m2; s = s2; return; }
    float M = fmaxf(m, m2);
    s = s * expf(m - M) + s2 * expf(m2 - M);
    m = M;
}

// SIMPLE interleaved 2-row dot — the R2 shape measured at 2.66 TB/s.
template <int N4>
__device__ __forceinline__ void dot2simple(const float4* __restrict__ row0,
                                           const float4* __restrict__ row1,
                                           const float4* __restrict__ v4,
                                           int lane, float& a0, float& a1) {
#pragma unroll 4
    for (int j = lane; j < N4; j += 32) {
        float4 c = v4[j];
        float4 x = row0[j];
        float4 y = row1[j];
        a0 += x.x * c.x + x.y * c.y + x.z * c.z + x.w * c.w;
        a1 += y.x * c.x + y.y * c.y + y.z * c.z + y.w * c.w;
    }
}

// Front-batched variant — ONLY for k_out's long strips (measured ~6.9 TB/s).
template <int NF4, int G>
__device__ __forceinline__ void dot2rows(const float4* __restrict__ row0,
                                         const float4* __restrict__ row1,
                                         const float4* __restrict__ v4,
                                         int lane, float& a0, float& a1) {
#pragma unroll
    for (int g = 0; g < NF4 / G; g++) {
        float4 xa[G], ya[G];
#pragma unroll
        for (int u = 0; u < G; u++) {
            int j = lane + (g * G + u) * 32;
            xa[u] = __ldcs(row0 + j);
            ya[u] = __ldcs(row1 + j);
        }
#pragma unroll
        for (int u = 0; u < G; u++) {
            int j = lane + (g * G + u) * 32;
            float4 c = v4[j];
            a0 += xa[u].x * c.x + xa[u].y * c.y + xa[u].z * c.z + xa[u].w * c.w;
            a1 += ya[u].x * c.x + ya[u].y * c.y + ya[u].z * c.z + ya[u].w * c.w;
        }
    }
}

// K1: emb = linear_w @ emb_row + b  (512 pair-tasks)  AND
//     gh  = gru_whh @ h0 + bhh      (1536 pair-tasks). 256 blocks = 2048 warps.
__global__ void __launch_bounds__(256)
k1_emb_gh(const int* __restrict__ token, const float* __restrict__ emb_table,
          const float* __restrict__ linear_w, const float* __restrict__ linear_b,
          const float* __restrict__ gru_whh, const float* __restrict__ gru_bhh,
          const float* __restrict__ hidden) {
    __shared__ float svec[2 * H];
    const int tid = threadIdx.x;
    const int warp = tid >> 5, lane = tid & 31;
    const float* erow = emb_table + (size_t)token[0] * E;
    for (int i = tid; i < H; i += 256) {
        svec[i]     = erow[i];
        svec[H + i] = hidden[i];
    }
    __syncthreads();
    const float4* v4 = (const float4*)svec;
    int wgid = blockIdx.x * 8 + warp;              // 0..2047
    if (wgid < 512) {
        int r0 = wgid * 2;
        const float4* row0 = (const float4*)(linear_w + (size_t)r0 * E);
        const float4* row1 = (const float4*)(linear_w + (size_t)(r0 + 1) * E);
        float a0 = 0.f, a1 = 0.f;
        dot2simple<256>(row0, row1, v4, lane, a0, a1);
        a0 = warp_reduce_sum(a0);
        a1 = warp_reduce_sum(a1);
        if (lane == 0) {
            g_emb[r0]     = a0 + linear_b[r0];
            g_emb[r0 + 1] = a1 + linear_b[r0 + 1];
        }
    } else {
        int r0 = (wgid - 512) * 2;
        const float4* row0 = (const float4*)(gru_whh + (size_t)r0 * H);
        const float4* row1 = (const float4*)(gru_whh + (size_t)(r0 + 1) * H);
        float a0 = 0.f, a1 = 0.f;
        dot2simple<256>(row0, row1, v4 + H / 4, lane, a0, a1);
        a0 = warp_reduce_sum(a0);
        a1 = warp_reduce_sum(a1);
        if (lane == 0) {
            g_gh[r0]     = a0 + gru_bhh[r0];
            g_gh[r0 + 1] = a1 + gru_bhh[r0 + 1];
        }
    }
}

// K2: full attention in one kernel. 4 blocks; EACH block redundantly computes
// all 52 logits (0.2MB reads, L2-shared across blocks), softmaxes locally,
// then applies its 256-col slice of attn_applied. No cross-block sync needed.
__global__ void __launch_bounds__(256)
k2_attn(const float* __restrict__ hidden,
        const float* __restrict__ attn_w, const float* __restrict__ attn_b,
        const float* __restrict__ enc, float* __restrict__ out_aw) {
    __shared__ float sv[2 * H];
    __shared__ float slog[L];
    __shared__ float sw[L];
    const int tid = threadIdx.x;
    const int warp = tid >> 5, lane = tid & 31;
    for (int i = tid; i < H; i += 256) {
        sv[i]     = g_emb[i];
        sv[H + i] = hidden[i];
    }
    __syncthreads();
    const float4* v4 = (const float4*)sv;
    for (int p = warp; p < 26; p += 8) {
        int r0 = p * 2;
        const float4* row0 = (const float4*)(attn_w + (size_t)r0 * 2 * H);
        const float4* row1 = (const float4*)(attn_w + (size_t)(r0 + 1) * 2 * H);
        float a0 = 0.f, a1 = 0.f;
        dot2simple<512>(row0, row1, v4, lane, a0, a1);
        a0 = warp_reduce_sum(a0);
        a1 = warp_reduce_sum(a1);
        if (lane == 0) {
            slog[r0]     = a0 + attn_b[r0];
            slog[r0 + 1] = a1 + attn_b[r0 + 1];
        }
    }
    __syncthreads();
    if (tid == 0) {
        float m = slog[0];
        for (int i = 1; i < L; i++) m = fmaxf(m, slog[i]);
        float s = 0.f;
        for (int i = 0; i < L; i++) { float e = expf(slog[i] - m); sw[i] = e; s += e; }
        float inv = 1.f / s;
        for (int i = 0; i < L; i++) sw[i] *= inv;
    }
    __syncthreads();
    int h = blockIdx.x * 256 + tid;
    float acc = 0.f;
#pragma unroll
    for (int l = 0; l < L; l++) acc += sw[l] * enc[l * H + h];
    g_attn[h] = acc;
    if (blockIdx.x == 0 && tid < L) out_aw[tid] = sw[tid];
}

// K3: comb partials, K-split. 128 blocks = 1024 tasks (pair = t>>1, sp = t&1).
__global__ void __launch_bounds__(256)
k3_comb(const float* __restrict__ comb_w, const float* __restrict__ hidden) {
    __shared__ float svec[2 * H];
    const int tid = threadIdx.x;
    const int warp = tid >> 5, lane = tid & 31;
    for (int i = tid; i < H; i += 256) {
        svec[i]     = g_emb[i];
        svec[H + i] = g_attn[i];
    }
    __syncthreads();
    const float4* v4 = (const float4*)svec;
    int t = blockIdx.x * 8 + warp;                 // 0..1023
    int r0 = (t >> 1) * 2, sp = t & 1;
    const float4* row0 = (const float4*)(comb_w + (size_t)r0 * 2 * H + sp * H);
    const float4* row1 = (const float4*)(comb_w + (size_t)(r0 + 1) * 2 * H + sp * H);
    float a0 = 0.f, a1 = 0.f;
    dot2simple<256>(row0, row1, v4 + sp * (H / 4), lane, a0, a1);
    a0 = warp_reduce_sum(a0);
    a1 = warp_reduce_sum(a1);
    if (lane == 0) {
        g_x_p[sp * H + r0]     = a0;
        g_x_p[sp * H + r0 + 1] = a1;
    }
}

// K4: gi = gru_wih @ x + bih. 192 blocks = 1536 pair-tasks.
// x = relu(partials + comb_b) built during staging.
__global__ void __launch_bounds__(256)
k4_gi(const float* __restrict__ gru_wih, const float* __restrict__ gru_bih,
      const float* __restrict__ comb_b) {
    __shared__ float sx[H];
    const int tid = threadIdx.x;
    const int warp = tid >> 5, lane = tid & 31;
    for (int i = tid; i < H; i += 256)
        sx[i] = fmaxf(g_x_p[i] + g_x_p[H + i] + comb_b[i], 0.f);
    __syncthreads();
    const float4* v4 = (const float4*)sx;
    int r0 = (blockIdx.x * 8 + warp) * 2;
    const float4* row0 = (const float4*)(gru_wih + (size_t)r0 * H);
    const float4* row1 = (const float4*)(gru_wih + (size_t)(r0 + 1) * H);
    float a0 = 0.f, a1 = 0.f;
    dot2simple<256>(row0, row1, v4, lane, a0, a1);
    a0 = warp_reduce_sum(a0);
    a1 = warp_reduce_sum(a1);
    if (lane == 0) {
        g_gi[r0]     = a0 + gru_bih[r0];
        g_gi[r0 + 1] = a1 + gru_bih[r0 + 1];
    }
}

// K5: GRU combine (inline, redundant per block) + vocab GEMV at LTS cap.
// Each block computes h_new from g_gi/g_gh/h0 during staging (28KB L2 reads).
__global__ void __launch_bounds__(256, 3)
k_out(const float* __restrict__ W, const float* __restrict__ b,
      const float* __restrict__ hidden,
      float* __restrict__ out, float* __restrict__ out_h) {
    __shared__ float sv[H];
    __shared__ float wm[8], ws[8];
    for (int i = threadIdx.x; i < H; i += 256) {
        float ir = g_gi[i], iz = g_gi[H + i], inn = g_gi[2 * H + i];
        float hr = g_gh[i], hz = g_gh[H + i], hn = g_gh[2 * H + i];
        float r = 1.f / (1.f + expf(-(ir + hr)));
        float z = 1.f / (1.f + expf(-(iz + hz)));
        float n = tanhf(inn + r * hn);
        float hv = (1.f - z) * n + z * hidden[i];
        sv[i] = hv;
        if (blockIdx.x == 0) out_h[i] = hv;
    }
    __syncthreads();
    int warp = threadIdx.x >> 5, lane = threadIdx.x & 31;
    const float4* v4 = (const float4*)sv;
    int base = (blockIdx.x * 8 + warp) * OUT_CHUNK;
    float m_w = -INFINITY, s_w = 0.f;
#pragma unroll
    for (int pr = 0; pr < OUT_CHUNK / 2; pr++) {
        int r0 = base + 2 * pr;
        if (r0 >= V) break;
        int r1c = min(r0 + 1, V - 1);
        const float4* row0 = (const float4*)(W + (size_t)r0 * H);
        const float4* row1 = (const float4*)(W + (size_t)r1c * H);
        float a0 = 0.f, a1 = 0.f;
        dot2rows<8, 4>(row0, row1, v4, lane, a0, a1);
        a0 = warp_reduce_sum(a0);
        a1 = warp_reduce_sum(a1);
        if (lane == 0) {
            float l0 = a0 + b[r0];
            out[r0] = l0;
            ms_merge(m_w, s_w, l0, 1.f);
            if (r0 + 1 < V) {
                float l1 = a1 + b[r0 + 1];
                out[r0 + 1] = l1;
                ms_merge(m_w, s_w, l1, 1.f);
            }
        }
    }
    if (lane == 0) { wm[warp] = m_w; ws[warp] = s_w; }
    __syncthreads();
    if (threadIdx.x == 0) {
        float m = -INFINITY, s = 0.f;
#pragma unroll
        for (int w = 0; w < 8; w++) ms_merge(m, s, wm[w], ws[w]);
        g_ms[blockIdx.x] = make_float2(m, s);
    }
}

// K6: merge per-block (m,s) -> lse, then subtract (log_softmax in place).
__global__ void __launch_bounds__(256)
k_sub(float* __restrict__ out) {
    __shared__ float sm[256], ss[256];
    float m = -INFINITY, s = 0.f;
    for (int i = threadIdx.x; i < OUT_BLOCKS; i += 256) {
        float2 p = g_ms[i];
        ms_merge(m, s, p.x, p.y);
    }
    sm[threadIdx.x] = m; ss[threadIdx.x] = s;
    __syncthreads();
    for (int st = 128; st; st >>= 1) {
        if (threadIdx.x < st) {
            float m1 = sm[threadIdx.x], s1 = ss[threadIdx.x];
            ms_merge(m1, s1, sm[threadIdx.x + st], ss[threadIdx.x + st]);
            sm[threadIdx.x] = m1; ss[threadIdx.x] = s1;
        }
        __syncthreads();
    }
    float lse = sm[0] + logf(ss[0]);
    for (int i = blockIdx.x * 256 + threadIdx.x; i < V; i += gridDim.x * 256)
        out[i] -= lse;
}

extern "C" void kernel_launch(void* const* d_in, const int* in_sizes, int n_in,
                              void* d_out, int out_size) {
    const int*   token     = (const int*)d_in[0];
    const float* hidden    = (const float*)d_in[1];
    const float* enc       = (const float*)d_in[2];
    const float* emb_table = (const float*)d_in[3];
    const float* linear_w  = (const float*)d_in[4];
    const float* linear_b  = (const float*)d_in[5];
    const float* attn_w    = (const float*)d_in[6];
    const float* attn_b    = (const float*)d_in[7];
    const float* comb_w    = (const float*)d_in[8];
    const float* comb_b    = (const float*)d_in[9];
    const float* gru_wih   = (const float*)d_in[10];
    const float* gru_whh   = (const float*)d_in[11];
    const float* gru_bih   = (const float*)d_in[12];
    const float* gru_bhh   = (const float*)d_in[13];
    const float* out_w     = (const float*)d_in[14];
    const float* out_b     = (const float*)d_in[15];

    float* out    = (float*)d_out;        // [0,V) log_probs
    float* out_h  = out + V;              // [V, V+H) h_new
    float* out_aw = out + V + H;          // [V+H, V+H+L) attn weights

    k1_emb_gh<<<256, 256>>>(token, emb_table, linear_w, linear_b,
                            gru_whh, gru_bhh, hidden);
    k2_attn<<<4, 256>>>(hidden, attn_w, attn_b, enc, out_aw);
    k3_comb<<<128, 256>>>(comb_w, hidden);
    k4_gi<<<192, 256>>>(gru_wih, gru_bih, comb_b);
    k_out<<<OUT_BLOCKS, 256>>>(out_w, out_b, hidden, out, out_h);
    k_sub<<<200, 256>>>(out);
}

// round 13
// speedup vs baseline: 1.0375x; 1.0375x over previous
#include <cuda_runtime.h>
#include <math.h>

#define V 50257
#define E 1024
#define H 1024
#define L 52

#define PRE_BLOCKS 296                     /* 2 blocks/SM x 148 SMs, co-resident */
#define OUT_CHUNK 16                       /* rows per warp in k_out */
#define OUT_BLOCKS 393                     /* ceil(V / (8*16)) */

// ---- device scratch (no allocs allowed) ----
__device__ float g_emb[H];
__device__ float g_attn[H];
__device__ float g_x_p[2 * H];      // comb partials (K-split)
__device__ float g_gi[3 * H];
__device__ float g_gh[3 * H];
__device__ float2 g_ms[OUT_BLOCKS]; // per-block online (max, sumexp)
__device__ int   g_cnt[4];          // barrier counters; reset by k_sub

__device__ __forceinline__ float warp_reduce_sum(float v) {
#pragma unroll
    for (int o = 16; o; o >>= 1) v += __shfl_down_sync(0xffffffffu, v, o);
    return v;
}

__device__ __forceinline__ void ms_merge(float& m, float& s, float m2, float s2) {
    if (s2 == 0.f) return;
    if (s == 0.f) { m = m2; s = s2; return; }
    float M = fmaxf(m, m2);
    s = s * expf(m - M) + s2 * expf(m2 - M);
    m = M;
}

// device-wide barrier (R8's measured-best atomic form)
__device__ __forceinline__ void gbar(int ph) {
    __syncthreads();
    if (threadIdx.x == 0) {
        __threadfence();
        atomicAdd(&g_cnt[ph], 1);
        volatile int* p = (volatile int*)&g_cnt[ph];
        while (*p < PRE_BLOCKS) { __nanosleep(64); }
        __threadfence();
    }
    __syncthreads();
}

// SIMPLE interleaved 2-row dot (low regs; measured-best shape for short tasks).
template <int N4>
__device__ __forceinline__ void dot2simple(const float4* __restrict__ row0,
                                           const float4* __restrict__ row1,
                                           const float4* __restrict__ v4,
                                           int lane, float& a0, float& a1) {
#pragma unroll 4
    for (int j = lane; j < N4; j += 32) {
        float4 c = v4[j];
        float4 x = __ldg(row0 + j);
        float4 y = __ldg(row1 + j);
        a0 += x.x * c.x + x.y * c.y + x.z * c.z + x.w * c.w;
        a1 += y.x * c.x + y.y * c.y + y.z * c.z + y.w * c.w;
    }
}

// Front-batched evict-first variant — ONLY for k_out's long strips (~6.9 TB/s).
template <int NF4, int G>
__device__ __forceinline__ void dot2rows(const float4* __restrict__ row0,
                                         const float4* __restrict__ row1,
                                         const float4* __restrict__ v4,
                                         int lane, float& a0, float& a1) {
#pragma unroll
    for (int g = 0; g < NF4 / G; g++) {
        float4 xa[G], ya[G];
#pragma unroll
        for (int u = 0; u < G; u++) {
            int j = lane + (g * G + u) * 32;
            xa[u] = __ldcs(row0 + j);
            ya[u] = __ldcs(row1 + j);
        }
#pragma unroll
        for (int u = 0; u < G; u++) {
            int j = lane + (g * G + u) * 32;
            float4 c = v4[j];
            a0 += xa[u].x * c.x + xa[u].y * c.y + xa[u].z * c.z + xa[u].w * c.w;
            a1 += ya[u].x * c.x + ya[u].y * c.y + ya[u].z * c.z + ya[u].w * c.w;
        }
    }
}

// ============================================================================
// K_PRE: persistent pre-vocab chain, 296 blocks, ONLY 3 device-wide barriers.
//  P0: emb (512 pairs, len E) + gh (1536 pairs, len H) — one round
//  [bar0]
//  P1: attention, sync-free: blocks 0..3 EACH redundantly compute all 52
//      logits + softmax, then apply their 256-col slice.
//  [bar1]
//  P2: comb partials K-split (1024 tasks)
//  [bar2]
//  P3: gi (1536 pairs)      (GRU combine folded into k_out staging)
// ============================================================================
__global__ void __launch_bounds__(256, 2)
k_pre(const int* __restrict__ token, const float* __restrict__ hidden,
      const float* __restrict__ enc, const float* __restrict__ emb_table,
      const float* __restrict__ linear_w, const float* __restrict__ linear_b,
      const float* __restrict__ attn_w, const float* __restrict__ attn_b,
      const float* __restrict__ comb_w, const float* __restrict__ comb_b,
      const float* __restrict__ gru_wih, const float* __restrict__ gru_whh,
      const float* __restrict__ gru_bih, const float* __restrict__ gru_bhh,
      float* __restrict__ out_aw) {
    __shared__ float svec[2 * H];
    __shared__ float slog[L];
    __shared__ float swt[L];
    const int tid = threadIdx.x;
    const int warp = tid >> 5, lane = tid & 31;
    const int bx = blockIdx.x;
    const float4* v4 = (const float4*)svec;

    // ---- stage: svec = [emb_table[token], hidden] ----
    const float* erow = emb_table + (size_t)token[0] * E;
    for (int i = tid; i < H; i += 256) {
        svec[i]     = erow[i];
        svec[H + i] = hidden[i];
    }
    __syncthreads();

    // ---- P0: 2048 tasks = emb(512) + gh(1536), one round per warp ----
    {
        int t = warp * PRE_BLOCKS + bx;            // 0..2367
        if (t < 512) {
            int r0 = t * 2;
            const float4* row0 = (const float4*)(linear_w + (size_t)r0 * E);
            const float4* row1 = (const float4*)(linear_w + (size_t)(r0 + 1) * E);
            float a0 = 0.f, a1 = 0.f;
            dot2simple<256>(row0, row1, v4, lane, a0, a1);
            a0 = warp_reduce_sum(a0);
            a1 = warp_reduce_sum(a1);
            if (lane == 0) {
                g_emb[r0]     = a0 + linear_b[r0];
                g_emb[r0 + 1] = a1 + linear_b[r0 + 1];
            }
        } else if (t < 2048) {
            int r0 = (t - 512) * 2;
            const float4* row0 = (const float4*)(gru_whh + (size_t)r0 * H);
            const float4* row1 = (const float4*)(gru_whh + (size_t)(r0 + 1) * H);
            float a0 = 0.f, a1 = 0.f;
            dot2simple<256>(row0, row1, v4 + H / 4, lane, a0, a1);
            a0 = warp_reduce_sum(a0);
            a1 = warp_reduce_sum(a1);
            if (lane == 0) {
                g_gh[r0]     = a0 + gru_bhh[r0];
                g_gh[r0 + 1] = a1 + gru_bhh[r0 + 1];
            }
        }
    }
    gbar(0);

    // ---- P1: sync-free attention on blocks 0..3 ----
    if (bx < 4) {
        for (int i = tid; i < H; i += 256) svec[i] = g_emb[i];   // [emb, h0]
        __syncthreads();
        for (int p = warp; p < 26; p += 8) {
            int r0 = p * 2;
            const float4* row0 = (const float4*)(attn_w + (size_t)r0 * 2 * H);
            const float4* row1 = (const float4*)(attn_w + (size_t)(r0 + 1) * 2 * H);
            float a0 = 0.f, a1 = 0.f;
            dot2simple<512>(row0, row1, v4, lane, a0, a1);
            a0 = warp_reduce_sum(a0);
            a1 = warp_reduce_sum(a1);
            if (lane == 0) {
                slog[r0]     = a0 + attn_b[r0];
                slog[r0 + 1] = a1 + attn_b[r0 + 1];
            }
        }
        __syncthreads();
        if (tid == 0) {
            float m = slog[0];
            for (int i = 1; i < L; i++) m = fmaxf(m, slog[i]);
            float s = 0.f;
            for (int i = 0; i < L; i++) { float e = expf(slog[i] - m); swt[i] = e; s += e; }
            float inv = 1.f / s;
            for (int i = 0; i < L; i++) swt[i] *= inv;
        }
        __syncthreads();
        int h = bx * 256 + tid;
        float acc = 0.f;
#pragma unroll
        for (int l = 0; l < L; l++) acc += swt[l] * enc[l * H + h];
        g_attn[h] = acc;
        if (bx == 0 && tid < L) out_aw[tid] = swt[tid];
    }
    gbar(1);

    // ---- stage: svec = [emb, attn_applied] ----
    for (int i = tid; i < H; i += 256) {
        svec[i]     = g_emb[i];
        svec[H + i] = g_attn[i];
    }
    __syncthreads();

    // ---- P2: comb partials K-split (1024 tasks, one round) ----
    {
        int t = warp * PRE_BLOCKS + bx;
        if (t < 1024) {
            int r0 = (t >> 1) * 2, sp = t & 1;
            const float4* row0 = (const float4*)(comb_w + (size_t)r0 * 2 * H + sp * H);
            const float4* row1 = (const float4*)(comb_w + (size_t)(r0 + 1) * 2 * H + sp * H);
            float a0 = 0.f, a1 = 0.f;
            dot2simple<256>(row0, row1, v4 + sp * (H / 4), lane, a0, a1);
            a0 = warp_reduce_sum(a0);
            a1 = warp_reduce_sum(a1);
            if (lane == 0) {
                g_x_p[sp * H + r0]     = a0;
                g_x_p[sp * H + r0 + 1] = a1;
            }
        }
    }
    gbar(2);

    // ---- stage: svec[0:H] = x = relu(partials + comb_b) ----
    for (int i = tid; i < H; i += 256)
        svec[i] = fmaxf(g_x_p[i] + g_x_p[H + i] + comb_b[i], 0.f);
    __syncthreads();

    // ---- P3: gi = gru_wih @ x + bih (1536 tasks, one round) ----
    {
        int t = warp * PRE_BLOCKS + bx;
        if (t < 1536) {
            int r0 = t * 2;
            const float4* row0 = (const float4*)(gru_wih + (size_t)r0 * H);
            const float4* row1 = (const float4*)(gru_wih + (size_t)(r0 + 1) * H);
            float a0 = 0.f, a1 = 0.f;
            dot2simple<256>(row0, row1, v4, lane, a0, a1);
            a0 = warp_reduce_sum(a0);
            a1 = warp_reduce_sum(a1);
            if (lane == 0) {
                g_gi[r0]     = a0 + gru_bih[r0];
                g_gi[r0 + 1] = a1 + gru_bih[r0 + 1];
            }
        }
    }
    // no trailing barrier: kernel boundary orders g_gi/g_gh before k_out
}

// ============================================================================
// K_OUT: GRU combine inline (redundant per block, 28KB L2 reads), then vocab
// GEMV at LTS cap with evict-first weights. Emits (max,sumexp) per block.
// ============================================================================
__global__ void __launch_bounds__(256, 3)
k_out(const float* __restrict__ W, const float* __restrict__ b,
      const float* __restrict__ hidden,
      float* __restrict__ out, float* __restrict__ out_h) {
    __shared__ float sv[H];
    __shared__ float wm[8], ws[8];
    for (int i = threadIdx.x; i < H; i += 256) {
        float ir = g_gi[i], iz = g_gi[H + i], inn = g_gi[2 * H + i];
        float hr = g_gh[i], hz = g_gh[H + i], hn = g_gh[2 * H + i];
        float r = 1.f / (1.f + expf(-(ir + hr)));
        float z = 1.f / (1.f + expf(-(iz + hz)));
        float n = tanhf(inn + r * hn);
        float hv = (1.f - z) * n + z * hidden[i];
        sv[i] = hv;
        if (blockIdx.x == 0) out_h[i] = hv;
    }
    __syncthreads();
    int warp = threadIdx.x >> 5, lane = threadIdx.x & 31;
    const float4* v4 = (const float4*)sv;
    int base = (blockIdx.x * 8 + warp) * OUT_CHUNK;
    float m_w = -INFINITY, s_w = 0.f;
#pragma unroll
    for (int pr = 0; pr < OUT_CHUNK / 2; pr++) {
        int r0 = base + 2 * pr;
        if (r0 >= V) break;
        int r1c = min(r0 + 1, V - 1);
        const float4* row0 = (const float4*)(W + (size_t)r0 * H);
        const float4* row1 = (const float4*)(W + (size_t)r1c * H);
        float a0 = 0.f, a1 = 0.f;
        dot2rows<8, 4>(row0, row1, v4, lane, a0, a1);
        a0 = warp_reduce_sum(a0);
        a1 = warp_reduce_sum(a1);
        if (lane == 0) {
            float l0 = a0 + b[r0];
            out[r0] = l0;
            ms_merge(m_w, s_w, l0, 1.f);
            if (r0 + 1 < V) {
                float l1 = a1 + b[r0 + 1];
                out[r0 + 1] = l1;
                ms_merge(m_w, s_w, l1, 1.f);
            }
        }
    }
    if (lane == 0) { wm[warp] = m_w; ws[warp] = s_w; }
    __syncthreads();
    if (threadIdx.x == 0) {
        float m = -INFINITY, s = 0.f;
#pragma unroll
        for (int w = 0; w < 8; w++) ms_merge(m, s, wm[w], ws[w]);
        g_ms[blockIdx.x] = make_float2(m, s);
    }
}

// K_SUB: merge per-block (m,s) -> lse, subtract in place; reset barriers.
__global__ void __launch_bounds__(256)
k_sub(float* __restrict__ out) {
    if (blockIdx.x == 0 && threadIdx.x < 4) g_cnt[threadIdx.x] = 0;  // next replay
    __shared__ float sm[256], ss[256];
    float m = -INFINITY, s = 0.f;
    for (int i = threadIdx.x; i < OUT_BLOCKS; i += 256) {
        float2 p = g_ms[i];
        ms_merge(m, s, p.x, p.y);
    }
    sm[threadIdx.x] = m; ss[threadIdx.x] = s;
    __syncthreads();
    for (int st = 128; st; st >>= 1) {
        if (threadIdx.x < st) {
            float m1 = sm[threadIdx.x], s1 = ss[threadIdx.x];
            ms_merge(m1, s1, sm[threadIdx.x + st], ss[threadIdx.x + st]);
            sm[threadIdx.x] = m1; ss[threadIdx.x] = s1;
        }
        __syncthreads();
    }
    float lse = sm[0] + logf(ss[0]);
    for (int i = blockIdx.x * 256 + threadIdx.x; i < V; i += gridDim.x * 256)
        out[i] -= lse;
}

extern "C" void kernel_launch(void* const* d_in, const int* in_sizes, int n_in,
                              void* d_out, int out_size) {
    const int*   token     = (const int*)d_in[0];
    const float* hidden    = (const float*)d_in[1];
    const float* enc       = (const float*)d_in[2];
    const float* emb_table = (const float*)d_in[3];
    const float* linear_w  = (const float*)d_in[4];
    const float* linear_b  = (const float*)d_in[5];
    const float* attn_w    = (const float*)d_in[6];
    const float* attn_b    = (const float*)d_in[7];
    const float* comb_w    = (const float*)d_in[8];
    const float* comb_b    = (const float*)d_in[9];
    const float* gru_wih   = (const float*)d_in[10];
    const float* gru_whh   = (const float*)d_in[11];
    const float* gru_bih   = (const float*)d_in[12];
    const float* gru_bhh   = (const float*)d_in[13];
    const float* out_w     = (const float*)d_in[14];
    const float* out_b     = (const float*)d_in[15];

    float* out    = (float*)d_out;        // [0,V) log_probs
    float* out_h  = out + V;              // [V, V+H) h_new
    float* out_aw = out + V + H;          // [V+H, V+H+L) attn weights

    k_pre<<<PRE_BLOCKS, 256>>>(token, hidden, enc, emb_table,
                               linear_w, linear_b, attn_w, attn_b,
                               comb_w, comb_b, gru_wih, gru_whh,
                               gru_bih, gru_bhh, out_aw);
    k_out<<<OUT_BLOCKS, 256>>>(out_w, out_b, hidden, out, out_h);
    k_sub<<<200, 256>>>(out);
}

// round 14
// speedup vs baseline: 1.0997x; 1.0599x over previous
#include <cuda_runtime.h>
#include <math.h>

#define V 50257
#define E 1024
#define H 1024
#define L 52

#define PRE_BLOCKS 296                     /* 2 blocks/SM x 148 SMs, co-resident */
#define OUT_CHUNK 16                       /* rows per warp in k_out */
#define OUT_BLOCKS 393                     /* ceil(V / (8*16)) */

// ---- device scratch (no allocs allowed) ----
__device__ float g_emb[H];
__device__ float g_attn[H];
__device__ float g_x_p[2 * H];      // comb partials (K-split)
__device__ float g_alog[L];
__device__ float g_gi[3 * H];
__device__ float g_gh[3 * H];
__device__ float2 g_ms[OUT_BLOCKS]; // per-block online (max, sumexp)
__device__ int   g_cnt[4];          // barrier counters; reset by k_sub

__device__ __forceinline__ float warp_reduce_sum(float v) {
#pragma unroll
    for (int o = 16; o; o >>= 1) v += __shfl_down_sync(0xffffffffu, v, o);
    return v;
}

__device__ __forceinline__ void ms_merge(float& m, float& s, float m2, float s2) {
    if (s2 == 0.f) return;
    if (s == 0.f) { m = m2; s = s2; return; }
    float M = fmaxf(m, m2);
    s = s * expf(m - M) + s2 * expf(m2 - M);
    m = M;
}

// device-wide barrier: atomic arrival (R8 form) + SLOW poll (512ns) to avoid
// LTS-slice saturation from 296 concurrent pollers on one line.
__device__ __forceinline__ void gbar(int ph) {
    __syncthreads();
    if (threadIdx.x == 0) {
        __threadfence();
        atomicAdd(&g_cnt[ph], 1);
        volatile int* p = (volatile int*)&g_cnt[ph];
        while (*p < PRE_BLOCKS) { __nanosleep(512); }
        __threadfence();
    }
    __syncthreads();
}

// SIMPLE interleaved 2-row dot (low regs; measured-best shape for short tasks).
template <int N4>
__device__ __forceinline__ void dot2simple(const float4* __restrict__ row0,
                                           const float4* __restrict__ row1,
                                           const float4* __restrict__ v4,
                                           int lane, float& a0, float& a1) {
#pragma unroll 4
    for (int j = lane; j < N4; j += 32) {
        float4 c = v4[j];
        float4 x = __ldg(row0 + j);
        float4 y = __ldg(row1 + j);
        a0 += x.x * c.x + x.y * c.y + x.z * c.z + x.w * c.w;
        a1 += y.x * c.x + y.y * c.y + y.z * c.z + y.w * c.w;
    }
}

// Front-batched evict-first variant — ONLY for k_out's long strips (~6.9 TB/s).
template <int NF4, int G>
__device__ __forceinline__ void dot2rows(const float4* __restrict__ row0,
                                         const float4* __restrict__ row1,
                                         const float4* __restrict__ v4,
                                         int lane, float& a0, float& a1) {
#pragma unroll
    for (int g = 0; g < NF4 / G; g++) {
        float4 xa[G], ya[G];
#pragma unroll
        for (int u = 0; u < G; u++) {
            int j = lane + (g * G + u) * 32;
            xa[u] = __ldcs(row0 + j);
            ya[u] = __ldcs(row1 + j);
        }
#pragma unroll
        for (int u = 0; u < G; u++) {
            int j = lane + (g * G + u) * 32;
            float4 c = v4[j];
            a0 += xa[u].x * c.x + xa[u].y * c.y + xa[u].z * c.z + xa[u].w * c.w;
            a1 += ya[u].x * c.x + ya[u].y * c.y + ya[u].z * c.z + ya[u].w * c.w;
        }
    }
}

// gh pair-task u (0..1535): rows 2u, 2u+1 of gru_whh vs h0 (svec[H:2H]).
__device__ __forceinline__ void gh_task(int u, const float* __restrict__ gru_whh,
                                        const float* __restrict__ gru_bhh,
                                        const float4* __restrict__ v4, int lane) {
    int r0 = u * 2;
    const float4* row0 = (const float4*)(gru_whh + (size_t)r0 * H);
    const float4* row1 = (const float4*)(gru_whh + (size_t)(r0 + 1) * H);
    float a0 = 0.f, a1 = 0.f;
    dot2simple<256>(row0, row1, v4 + H / 4, lane, a0, a1);
    a0 = warp_reduce_sum(a0);
    a1 = warp_reduce_sum(a1);
    if (lane == 0) {
        g_gh[r0]     = a0 + gru_bhh[r0];
        g_gh[r0 + 1] = a1 + gru_bhh[r0 + 1];
    }
}

// ============================================================================
// K_PRE: R8's balanced phase layout, 4 barriers, slow-poll.
//  P0: emb (512 pairs, len E) + gh[0..768)    — all blocks busy
//  P1: attn logits (26 pairs) + gh[768..1152) — all blocks busy
//  P2: softmax+apply (blocks 0-3) + gh[1152..1536) (blocks >=4)
//  P3: comb partials K-split (1024 tasks)
//  P4: gi (1536 pairs)      (GRU combine folded into k_out staging)
// ============================================================================
__global__ void __launch_bounds__(256, 2)
k_pre(const int* __restrict__ token, const float* __restrict__ hidden,
      const float* __restrict__ enc, const float* __restrict__ emb_table,
      const float* __restrict__ linear_w, const float* __restrict__ linear_b,
      const float* __restrict__ attn_w, const float* __restrict__ attn_b,
      const float* __restrict__ comb_w, const float* __restrict__ comb_b,
      const float* __restrict__ gru_wih, const float* __restrict__ gru_whh,
      const float* __restrict__ gru_bih, const float* __restrict__ gru_bhh,
      float* __restrict__ out_aw) {
    __shared__ float svec[2 * H];
    __shared__ float sw[L];
    const int tid = threadIdx.x;
    const int warp = tid >> 5, lane = tid & 31;
    const int bx = blockIdx.x;
    const float4* v4 = (const float4*)svec;

    // ---- stage 0: svec = [emb_table[token], hidden] ----
    const float* erow = emb_table + (size_t)token[0] * E;
    for (int i = tid; i < H; i += 256) {
        svec[i]     = erow[i];
        svec[H + i] = hidden[i];
    }
    __syncthreads();

    // ---- P0: 1280 tasks = emb(512) + gh[0..768), one round ----
    {
        int t = warp * PRE_BLOCKS + bx;            // 0..2367
        if (t < 512) {
            int r0 = t * 2;
            const float4* row0 = (const float4*)(linear_w + (size_t)r0 * E);
            const float4* row1 = (const float4*)(linear_w + (size_t)(r0 + 1) * E);
            float a0 = 0.f, a1 = 0.f;
            dot2simple<256>(row0, row1, v4, lane, a0, a1);
            a0 = warp_reduce_sum(a0);
            a1 = warp_reduce_sum(a1);
            if (lane == 0) {
                g_emb[r0]     = a0 + linear_b[r0];
                g_emb[r0 + 1] = a1 + linear_b[r0 + 1];
            }
        } else if (t < 1280) {
            gh_task(t - 512, gru_whh, gru_bhh, v4, lane);
        }
    }
    gbar(0);

    // ---- stage 1: svec[0:H] = final emb (h0 stays at [H:2H]) ----
    for (int i = tid; i < H; i += 256) svec[i] = g_emb[i];
    __syncthreads();

    // ---- P1: attn logits on warp 7 of blocks 0..25; gh[768..1152) filler ----
    if (warp == 7 && bx < 26) {
        int r0 = bx * 2;
        const float4* row0 = (const float4*)(attn_w + (size_t)r0 * 2 * H);
        const float4* row1 = (const float4*)(attn_w + (size_t)(r0 + 1) * 2 * H);
        float a0 = 0.f, a1 = 0.f;
        dot2simple<512>(row0, row1, v4, lane, a0, a1);
        a0 = warp_reduce_sum(a0);
        a1 = warp_reduce_sum(a1);
        if (lane == 0) {
            g_alog[r0]     = a0 + attn_b[r0];
            g_alog[r0 + 1] = a1 + attn_b[r0 + 1];
        }
    } else {
        for (int t = warp * PRE_BLOCKS + bx; t < 384; t += 7 * PRE_BLOCKS)
            gh_task(768 + t, gru_whh, gru_bhh, v4, lane);
    }
    gbar(1);

    // ---- P2: softmax+apply on blocks 0..3; gh[1152..1536) on blocks >=4 ----
    if (bx < 4) {
        if (tid == 0) {
            float m = g_alog[0];
            for (int i = 1; i < L; i++) m = fmaxf(m, g_alog[i]);
            float s = 0.f;
            for (int i = 0; i < L; i++) { float e = expf(g_alog[i] - m); sw[i] = e; s += e; }
            float inv = 1.f / s;
            for (int i = 0; i < L; i++) sw[i] *= inv;
        }
        __syncthreads();
        int h = bx * 256 + tid;
        float acc = 0.f;
#pragma unroll
        for (int l = 0; l < L; l++) acc += sw[l] * enc[l * H + h];
        g_attn[h] = acc;
        if (bx == 0 && tid < L) out_aw[tid] = sw[tid];
    } else {
        for (int t = warp * (PRE_BLOCKS - 4) + (bx - 4); t < 384; t += 8 * (PRE_BLOCKS - 4))
            gh_task(1152 + t, gru_whh, gru_bhh, v4, lane);
    }
    gbar(2);

    // ---- stage 3: svec[H:2H] = attn_applied (emb stays at [0:H]) ----
    for (int i = tid; i < H; i += 256) svec[H + i] = g_attn[i];
    __syncthreads();

    // ---- P3: comb partials K-split (1024 tasks, one round) ----
    {
        int t = warp * PRE_BLOCKS + bx;
        if (t < 1024) {
            int r0 = (t >> 1) * 2, sp = t & 1;
            const float4* row0 = (const float4*)(comb_w + (size_t)r0 * 2 * H + sp * H);
            const float4* row1 = (const float4*)(comb_w + (size_t)(r0 + 1) * 2 * H + sp * H);
            float a0 = 0.f, a1 = 0.f;
            dot2simple<256>(row0, row1, v4 + sp * (H / 4), lane, a0, a1);
            a0 = warp_reduce_sum(a0);
            a1 = warp_reduce_sum(a1);
            if (lane == 0) {
                g_x_p[sp * H + r0]     = a0;
                g_x_p[sp * H + r0 + 1] = a1;
            }
        }
    }
    gbar(3);

    // ---- stage 4: svec[0:H] = x = relu(partials + comb_b) ----
    for (int i = tid; i < H; i += 256)
        svec[i] = fmaxf(g_x_p[i] + g_x_p[H + i] + comb_b[i], 0.f);
    __syncthreads();

    // ---- P4: gi = gru_wih @ x + bih (1536 tasks, one round) ----
    {
        int t = warp * PRE_BLOCKS + bx;
        if (t < 1536) {
            int r0 = t * 2;
            const float4* row0 = (const float4*)(gru_wih + (size_t)r0 * H);
            const float4* row1 = (const float4*)(gru_wih + (size_t)(r0 + 1) * H);
            float a0 = 0.f, a1 = 0.f;
            dot2simple<256>(row0, row1, v4, lane, a0, a1);
            a0 = warp_reduce_sum(a0);
            a1 = warp_reduce_sum(a1);
            if (lane == 0) {
                g_gi[r0]     = a0 + gru_bih[r0];
                g_gi[r0 + 1] = a1 + gru_bih[r0 + 1];
            }
        }
    }
    // no trailing barrier: kernel boundary orders g_gi/g_gh before k_out
}

// ============================================================================
// K_OUT: GRU combine inline (redundant per block, ~28KB L2 reads), then vocab
// GEMV at LTS cap with evict-first weights. Emits (max,sumexp) per block.
// ============================================================================
__global__ void __launch_bounds__(256, 3)
k_out(const float* __restrict__ W, const float* __restrict__ b,
      const float* __restrict__ hidden,
      float* __restrict__ out, float* __restrict__ out_h) {
    __shared__ float sv[H];
    __shared__ float wm[8], ws[8];
    for (int i = threadIdx.x; i < H; i += 256) {
        float ir = g_gi[i], iz = g_gi[H + i], inn = g_gi[2 * H + i];
        float hr = g_gh[i], hz = g_gh[H + i], hn = g_gh[2 * H + i];
        float r = 1.f / (1.f + expf(-(ir + hr)));
        float z = 1.f / (1.f + expf(-(iz + hz)));
        float n = tanhf(inn + r * hn);
        float hv = (1.f - z) * n + z * hidden[i];
        sv[i] = hv;
        if (blockIdx.x == 0) out_h[i] = hv;
    }
    __syncthreads();
    int warp = threadIdx.x >> 5, lane = threadIdx.x & 31;
    const float4* v4 = (const float4*)sv;
    int base = (blockIdx.x * 8 + warp) * OUT_CHUNK;
    float m_w = -INFINITY, s_w = 0.f;
#pragma unroll
    for (int pr = 0; pr < OUT_CHUNK / 2; pr++) {
        int r0 = base + 2 * pr;
        if (r0 >= V) break;
        int r1c = min(r0 + 1, V - 1);
        const float4* row0 = (const float4*)(W + (size_t)r0 * H);
        const float4* row1 = (const float4*)(W + (size_t)r1c * H);
        float a0 = 0.f, a1 = 0.f;
        dot2rows<8, 4>(row0, row1, v4, lane, a0, a1);
        a0 = warp_reduce_sum(a0);
        a1 = warp_reduce_sum(a1);
        if (lane == 0) {
            float l0 = a0 + b[r0];
            out[r0] = l0;
            ms_merge(m_w, s_w, l0, 1.f);
            if (r0 + 1 < V) {
                float l1 = a1 + b[r0 + 1];
                out[r0 + 1] = l1;
                ms_merge(m_w, s_w, l1, 1.f);
            }
        }
    }
    if (lane == 0) { wm[warp] = m_w; ws[warp] = s_w; }
    __syncthreads();
    if (threadIdx.x == 0) {
        float m = -INFINITY, s = 0.f;
#pragma unroll
        for (int w = 0; w < 8; w++) ms_merge(m, s, wm[w], ws[w]);
        g_ms[blockIdx.x] = make_float2(m, s);
    }
}

// K_SUB: merge per-block (m,s) -> lse, subtract in place; reset barriers.
__global__ void __launch_bounds__(256)
k_sub(float* __restrict__ out) {
    if (blockIdx.x == 0 && threadIdx.x < 4) g_cnt[threadIdx.x] = 0;  // next replay
    __shared__ float sm[256], ss[256];
    float m = -INFINITY, s = 0.f;
    for (int i = threadIdx.x; i < OUT_BLOCKS; i += 256) {
        float2 p = g_ms[i];
        ms_merge(m, s, p.x, p.y);
    }
    sm[threadIdx.x] = m; ss[threadIdx.x] = s;
    __syncthreads();
    for (int st = 128; st; st >>= 1) {
        if (threadIdx.x < st) {
            float m1 = sm[threadIdx.x], s1 = ss[threadIdx.x];
            ms_merge(m1, s1, sm[threadIdx.x + st], ss[threadIdx.x + st]);
            sm[threadIdx.x] = m1; ss[threadIdx.x] = s1;
        }
        __syncthreads();
    }
    float lse = sm[0] + logf(ss[0]);
    for (int i = blockIdx.x * 256 + threadIdx.x; i < V; i += gridDim.x * 256)
        out[i] -= lse;
}

extern "C" void kernel_launch(void* const* d_in, const int* in_sizes, int n_in,
                              void* d_out, int out_size) {
    const int*   token     = (const int*)d_in[0];
    const float* hidden    = (const float*)d_in[1];
    const float* enc       = (const float*)d_in[2];
    const float* emb_table = (const float*)d_in[3];
    const float* linear_w  = (const float*)d_in[4];
    const float* linear_b  = (const float*)d_in[5];
    const float* attn_w    = (const float*)d_in[6];
    const float* attn_b    = (const float*)d_in[7];
    const float* comb_w    = (const float*)d_in[8];
    const float* comb_b    = (const float*)d_in[9];
    const float* gru_wih   = (const float*)d_in[10];
    const float* gru_whh   = (const float*)d_in[11];
    const float* gru_bih   = (const float*)d_in[12];
    const float* gru_bhh   = (const float*)d_in[13];
    const float* out_w     = (const float*)d_in[14];
    const float* out_b     = (const float*)d_in[15];

    float* out    = (float*)d_out;        // [0,V) log_probs
    float* out_h  = out + V;              // [V, V+H) h_new
    float* out_aw = out + V + H;          // [V+H, V+H+L) attn weights

    k_pre<<<PRE_BLOCKS, 256>>>(token, hidden, enc, emb_table,
                               linear_w, linear_b, attn_w, attn_b,
                               comb_w, comb_b, gru_wih, gru_whh,
                               gru_bih, gru_bhh, out_aw);
    k_out<<<OUT_BLOCKS, 256>>>(out_w, out_b, hidden, out, out_h);
    k_sub<<<200, 256>>>(out);
}